// round 1
// baseline (speedup 1.0000x reference)
#include <cuda_runtime.h>

// ---------------------------------------------------------------------------
// WaveletEncoder: 2-level Haar wavedec2 -> bilinear(antialias) resize to 8x8
// -> stack 7 maps -> [B,64,7] @ W[7,256] + b.
//
// Everything is linear & separable. The jax triangle-antialias resize weight
// w[o][i] = max(0, 1 - |s_o - i|/K) / tot(o),  K = N/8, s_o=(o+0.5)K-0.5,
// tot(o) = K for o=1..6, 0.875K for o=0,7 (boundary truncation),
// is exactly linear within blocks of K/2 elements (kinks & support ends land
// on block boundaries). So resize(sequence) needs only per-block (sum, ramp
// moment). Haar 1/sqrt(2) scales are folded into the resize coefficients
// (512-level tables get *INV_SQRT2, 256-level get *0.5), once per axis.
// ---------------------------------------------------------------------------

#define FULLMASK 0xffffffffu

__device__ float g_z[64u * 1024u * 32u];   // 8 MB: per-row resized col groups
__device__ float g_V[64u * 16u * 8u * 32u]; // 1 MB: row-axis block moments

// (a,b) such that w[o][block_start + u] = a + b*u within block t (size K/2).
static __device__ __forceinline__ void resize_ab(int o, int t, float K,
                                                 float invK, float fold,
                                                 float &a, float &b) {
    float tot = K * ((o == 0 || o == 7) ? 0.875f : 1.0f);
    float sf = (o + 0.5f) * K - 0.5f;
    float i0 = t * (K * 0.5f);
    float w0 = fmaxf(0.f, 1.f - fabsf(sf - i0) * invK);
    float w1 = fmaxf(0.f, 1.f - fabsf(sf - (i0 + 1.f)) * invK);
    float s = fold / tot;
    a = w0 * s;
    b = (w1 - w0) * s;
}

// Fill the 4 coefficient tables (8 outputs x 16 blocks, padded stride 17).
static __device__ __forceinline__ void fill_tables(int tid, float *tA512,
                                                   float *tB512, float *tA256,
                                                   float *tB256) {
    if (tid < 128) {
        int o = tid >> 4, t = tid & 15;
        float a, b;
        resize_ab(o, t, 64.f, 1.f / 64.f, 0.70710678118654752f, a, b);
        tA512[o * 17 + t] = a;
        tB512[o * 17 + t] = b;
    } else if (tid < 256) {
        int q = tid - 128;
        int o = q >> 4, t = q & 15;
        float a, b;
        resize_ab(o, t, 32.f, 1.f / 32.f, 0.5f, a, b);
        tA256[o * 17 + t] = a;
        tB256[o * 17 + t] = b;
    }
}

// ---------------------------------------------------------------------------
// Kernel 1: per image row, apply W-axis Haar + resize. One warp per row.
// Lane l owns columns [32l, 32l+32). Output: z[img][row][g*8+o], groups:
// g0=lo2res, g1=hi2res (256-table), g2=lo1res, g3=hi1res (512-table).
// ---------------------------------------------------------------------------
__global__ void __launch_bounds__(256) k1_rowpass(const float *__restrict__ x) {
    __shared__ float tA512[8 * 17], tB512[8 * 17], tA256[8 * 17], tB256[8 * 17];
    __shared__ float stg[8][8 * 17];  // per-warp: [8 moment types][16 blocks]

    int tid = threadIdx.x;
    fill_tables(tid, tA512, tB512, tA256, tB256);
    __syncthreads();

    int warp = tid >> 5, lane = tid & 31;
    int img = blockIdx.y;
    int row = (blockIdx.x << 3) + warp;

    const float4 *xv = reinterpret_cast<const float4 *>(
                           x + (((size_t)img << 20) + ((size_t)row << 10))) +
                       (lane << 3);

    float off = (float)((lane & 1) << 4);   // block-local offset for lo1/hi1
    float off2 = (float)((lane & 1) << 3);  // for lo2/hi2

    float s1 = 0, m1 = 0, s1h = 0, m1h = 0, s2 = 0, m2 = 0, s2h = 0, m2h = 0;

#pragma unroll
    for (int k = 0; k < 8; k++) {
        float4 v = xv[k];
        float loa = v.x + v.y, lob = v.z + v.w;  // unscaled haar lo (W level1)
        float hia = v.x - v.y, hib = v.z - v.w;  // unscaled haar hi
        float u = off + (float)(2 * k);
        s1 += loa + lob;
        m1 = fmaf(u, loa, m1);
        m1 = fmaf(u + 1.f, lob, m1);
        s1h += hia + hib;
        m1h = fmaf(u, hia, m1h);
        m1h = fmaf(u + 1.f, hib, m1h);
        float lo2 = loa + lob, hi2v = loa - lob;  // W level2 from lo1 pair
        float u2 = off2 + (float)k;
        s2 += lo2;
        m2 = fmaf(u2, lo2, m2);
        s2h += hi2v;
        m2h = fmaf(u2, hi2v, m2h);
    }

    // combine lane pairs -> block t = lane>>1 (16 blocks, all sequences)
    s1 += __shfl_xor_sync(FULLMASK, s1, 1);
    m1 += __shfl_xor_sync(FULLMASK, m1, 1);
    s1h += __shfl_xor_sync(FULLMASK, s1h, 1);
    m1h += __shfl_xor_sync(FULLMASK, m1h, 1);
    s2 += __shfl_xor_sync(FULLMASK, s2, 1);
    m2 += __shfl_xor_sync(FULLMASK, m2, 1);
    s2h += __shfl_xor_sync(FULLMASK, s2h, 1);
    m2h += __shfl_xor_sync(FULLMASK, m2h, 1);

    float *sm = stg[warp];
    int t = lane >> 1;
    if (!(lane & 1)) {
        sm[0 * 17 + t] = s1;
        sm[1 * 17 + t] = m1;
        sm[2 * 17 + t] = s1h;
        sm[3 * 17 + t] = m1h;
        sm[4 * 17 + t] = s2;
        sm[5 * 17 + t] = m2;
        sm[6 * 17 + t] = s2h;
        sm[7 * 17 + t] = m2h;
    }
    __syncwarp();

    // 32 outputs: lane = g*8 + o
    int g = lane >> 3, o = lane & 7;
    const float *A = (g < 2) ? tA256 : tA512;
    const float *B = (g < 2) ? tB256 : tB512;
    int smt = ((g < 2) ? 4 : 0) + ((g & 1) << 1);  // g0->4 g1->6 g2->0 g3->2
    const float *S = sm + smt * 17;
    const float *M = sm + (smt + 1) * 17;
    float acc = 0.f;
#pragma unroll
    for (int tt = 0; tt < 16; tt++)
        acc = fmaf(A[o * 17 + tt], S[tt], fmaf(B[o * 17 + tt], M[tt], acc));

    g_z[(((size_t)img << 10) + row) * 32 + lane] = acc;
}

// ---------------------------------------------------------------------------
// Kernel 2a: H-axis Haar block moments. Warp per (img, 64-row block b).
// Lane = z-column. Coalesced 128B row reads. No shfl/smem needed: each
// 64-row block maps exactly onto one 32-block of lo1/hi1 and one 16-block
// of lo2/hi2.
// ---------------------------------------------------------------------------
__global__ void __launch_bounds__(256) k2a_colpass() {
    int tid = threadIdx.x, lane = tid & 31;
    int w = (blockIdx.x << 3) + (tid >> 5);  // 0..1023
    int img = w >> 4, b = w & 15;

    const float *zp = g_z + (((size_t)img << 10) + ((size_t)b << 6)) * 32 + lane;

    float s1 = 0, m1 = 0, s1h = 0, m1h = 0, s2 = 0, m2 = 0, s2h = 0, m2h = 0;
    float lop = 0.f;
#pragma unroll
    for (int k = 0; k < 32; k++) {
        float za = zp[(size_t)(k << 6)];
        float zb = zp[(size_t)(k << 6) + 32];
        float lo = za + zb, hi = za - zb;
        float fk = (float)k;
        s1 += lo;
        m1 = fmaf(fk, lo, m1);
        s1h += hi;
        m1h = fmaf(fk, hi, m1h);
        if (k & 1) {
            float lo2 = lop + lo, hi2 = lop - lo;
            float u2 = (float)(k >> 1);
            s2 += lo2;
            m2 = fmaf(u2, lo2, m2);
            s2h += hi2;
            m2h = fmaf(u2, hi2, m2h);
        } else {
            lop = lo;
        }
    }

    float *vp = g_V + (((size_t)(img * 16 + b)) << 8) + lane;
    vp[0] = s1;
    vp[32] = m1;
    vp[64] = s1h;
    vp[96] = m1h;
    vp[128] = s2;
    vp[160] = m2;
    vp[192] = s2h;
    vp[224] = m2h;
}

// ---------------------------------------------------------------------------
// Kernel 2b: per image: moments -> Y[32][32] -> feat(7 maps x 8x8) -> GEMM.
// ---------------------------------------------------------------------------
__global__ void __launch_bounds__(256)
    k2b_outpass(const float *__restrict__ Wg, const float *__restrict__ bias,
                float *__restrict__ out) {
    __shared__ float tA512[8 * 17], tB512[8 * 17], tA256[8 * 17], tB256[8 * 17];
    __shared__ float Vs[4096];     // [16 blocks][8 mt][32 cols]
    __shared__ float Ys[32 * 33];  // [row-group*8+o][col-group*8+oc], padded

    int tid = threadIdx.x;
    int img = blockIdx.x;
    fill_tables(tid, tA512, tB512, tA256, tB256);
    {
        const float4 *vg =
            reinterpret_cast<const float4 *>(g_V + ((size_t)img << 12));
        float4 *vs = reinterpret_cast<float4 *>(Vs);
#pragma unroll
        for (int i = 0; i < 4; i++) vs[tid + (i << 8)] = vg[tid + (i << 8)];
    }
    __syncthreads();

    // Stage 2: Y[ri][cb..cb+3]
    int ri = tid >> 3;
    int gr = ri >> 3, o = ri & 7;
    int cb = (tid & 7) << 2;
    const float *A = (gr < 2) ? tA256 : tA512;
    const float *B = (gr < 2) ? tB256 : tB512;
    int smt = ((gr < 2) ? 4 : 0) + ((gr & 1) << 1);
    float a0 = 0, a1 = 0, a2 = 0, a3 = 0;
#pragma unroll
    for (int t = 0; t < 16; t++) {
        float av = A[o * 17 + t], bv = B[o * 17 + t];
        const float *S = Vs + ((t << 3) + smt) * 32 + cb;
        const float *M = S + 32;
        a0 = fmaf(av, S[0], fmaf(bv, M[0], a0));
        a1 = fmaf(av, S[1], fmaf(bv, M[1], a1));
        a2 = fmaf(av, S[2], fmaf(bv, M[2], a2));
        a3 = fmaf(av, S[3], fmaf(bv, M[3], a3));
    }
    Ys[ri * 33 + cb + 0] = a0;
    Ys[ri * 33 + cb + 1] = a1;
    Ys[ri * 33 + cb + 2] = a2;
    Ys[ri * 33 + cb + 3] = a3;
    __syncthreads();

    // Stage 3: out[img][p][c], thread = channel c. Map (rowgroup,colgroup):
    // cA2(0,0) cH2(1,0) cV2(0,1) cD2(1,1) cH1(3,2) cV1(2,3) cD1(3,3)
    float w0 = Wg[tid], w1 = Wg[256 + tid], w2 = Wg[512 + tid],
          w3 = Wg[768 + tid], w4 = Wg[1024 + tid], w5 = Wg[1280 + tid],
          w6 = Wg[1536 + tid];
    float bb = bias[tid];
    float *op = out + ((size_t)img << 14) + tid;
#pragma unroll
    for (int p = 0; p < 64; p++) {
        int i = p >> 3, j = p & 7;
        float v = bb;
        v = fmaf(Ys[(0 + i) * 33 + (0 + j)], w0, v);
        v = fmaf(Ys[(8 + i) * 33 + (0 + j)], w1, v);
        v = fmaf(Ys[(0 + i) * 33 + (8 + j)], w2, v);
        v = fmaf(Ys[(8 + i) * 33 + (8 + j)], w3, v);
        v = fmaf(Ys[(24 + i) * 33 + (16 + j)], w4, v);
        v = fmaf(Ys[(16 + i) * 33 + (24 + j)], w5, v);
        v = fmaf(Ys[(24 + i) * 33 + (24 + j)], w6, v);
        op[(size_t)p << 8] = v;
    }
}

extern "C" void kernel_launch(void *const *d_in, const int *in_sizes, int n_in,
                              void *d_out, int out_size) {
    const float *x = (const float *)d_in[0];     // [64,1,1024,1024]
    const float *W = (const float *)d_in[1];     // [7,256]
    const float *bias = (const float *)d_in[2];  // [256]
    float *out = (float *)d_out;                 // [64,64,256]

    dim3 g1(128, 64);
    k1_rowpass<<<g1, 256>>>(x);
    k2a_colpass<<<128, 256>>>();
    k2b_outpass<<<64, 256>>>(W, bias, out);
}

// round 2
// speedup vs baseline: 1.0273x; 1.0273x over previous
#include <cuda_runtime.h>

// ---------------------------------------------------------------------------
// WaveletEncoder: 2-level Haar wavedec2 -> bilinear(antialias) resize to 8x8
// -> stack 7 maps -> [B,64,7] @ W[7,256] + b.
//
// All-linear separable pipeline. Triangle antialias resize weight is linear
// within blocks of K/2 elements, so resize needs only per-block (sum, ramp
// moment). Haar 1/sqrt2 factors folded into resize coefficients per axis.
//
// Round-2 k1: zero shared memory. Per-lane analytic coefficients (g=0,1 share
// the 256 table; g=2,3 share the 512 table => 32 regs), partial z from each
// lane's own half-block moments, then 5-round shfl_xor butterfly whose output
// index bits equal lane bits => lane L ends holding z[L]. Warp-persistent
// over 32 rows.
// ---------------------------------------------------------------------------

#define FULLMASK 0xffffffffu

__device__ float g_z[64u * 1024u * 32u];    // 8 MB: per-row resized col groups
__device__ float g_V[64u * 16u * 8u * 32u]; // 1 MB: row-axis block moments

// (a,b) such that w[o][block_start + u] = a + b*u within block t (size K/2).
static __device__ __forceinline__ void resize_ab(int o, int t, float K,
                                                 float invK, float fold,
                                                 float &a, float &b) {
    float tot = K * ((o == 0 || o == 7) ? 0.875f : 1.0f);
    float sf = (o + 0.5f) * K - 0.5f;
    float i0 = t * (K * 0.5f);
    float w0 = fmaxf(0.f, 1.f - fabsf(sf - i0) * invK);
    float w1 = fmaxf(0.f, 1.f - fabsf(sf - (i0 + 1.f)) * invK);
    float s = fold / tot;
    a = w0 * s;
    b = (w1 - w0) * s;
}

// Table fill for k2b (unchanged path).
static __device__ __forceinline__ void fill_tables(int tid, float *tA512,
                                                   float *tB512, float *tA256,
                                                   float *tB256) {
    if (tid < 128) {
        int o = tid >> 4, t = tid & 15;
        float a, b;
        resize_ab(o, t, 64.f, 1.f / 64.f, 0.70710678118654752f, a, b);
        tA512[o * 17 + t] = a;
        tB512[o * 17 + t] = b;
    } else if (tid < 256) {
        int q = tid - 128;
        int o = q >> 4, t = q & 15;
        float a, b;
        resize_ab(o, t, 32.f, 1.f / 32.f, 0.5f, a, b);
        tA256[o * 17 + t] = a;
        tB256[o * 17 + t] = b;
    }
}

// ---------------------------------------------------------------------------
// Kernel 1: per image row, W-axis Haar + resize. Warp-persistent, smem-free.
// Lane l owns columns [32l, 32l+32) = half of block t=l>>1.
// Output z[img][row][g*8+o]: g0=lo2res, g1=hi2res, g2=lo1res, g3=hi1res.
// ---------------------------------------------------------------------------
__global__ void __launch_bounds__(128) k1_rowpass(const float *__restrict__ x) {
    const int lane = threadIdx.x & 31;
    const int gw = blockIdx.x * (blockDim.x >> 5) + (threadIdx.x >> 5);
    const int nwarps = gridDim.x * (blockDim.x >> 5);
    const int t = lane >> 1;

    // Per-lane coefficients at block t (32 registers).
    float A512[8], B512[8], A256[8], B256[8];
#pragma unroll
    for (int o = 0; o < 8; o++) {
        resize_ab(o, t, 64.f, 1.f / 64.f, 0.70710678118654752f, A512[o], B512[o]);
        resize_ab(o, t, 32.f, 1.f / 32.f, 0.5f, A256[o], B256[o]);
    }

    const float off = (float)((lane & 1) << 4);   // in-block offset (level 1)
    const float off2 = (float)((lane & 1) << 3);  // in-block offset (level 2)

    for (int r = gw; r < 64 * 1024; r += nwarps) {
        const float4 *xv =
            reinterpret_cast<const float4 *>(x + ((size_t)r << 10)) + (lane << 3);

        float4 v[8];
#pragma unroll
        for (int k = 0; k < 8; k++) v[k] = xv[k];  // front-batched: MLP=8

        float s1 = 0, m1 = 0, s1h = 0, m1h = 0, s2 = 0, m2 = 0, s2h = 0, m2h = 0;
#pragma unroll
        for (int k = 0; k < 8; k++) {
            float loa = v[k].x + v[k].y, lob = v[k].z + v[k].w;
            float hia = v[k].x - v[k].y, hib = v[k].z - v[k].w;
            float u = off + (float)(2 * k);
            s1 += loa + lob;
            m1 = fmaf(u, loa, m1);
            m1 = fmaf(u + 1.f, lob, m1);
            s1h += hia + hib;
            m1h = fmaf(u, hia, m1h);
            m1h = fmaf(u + 1.f, hib, m1h);
            float lo2 = loa + lob, hi2v = loa - lob;
            float u2 = off2 + (float)k;
            s2 += lo2;
            m2 = fmaf(u2, lo2, m2);
            s2h += hi2v;
            m2h = fmaf(u2, hi2v, m2h);
        }

        // Partial outputs from this lane's half-block moments.
        float acc[32];
#pragma unroll
        for (int o = 0; o < 8; o++) {
            acc[o]      = fmaf(A256[o], s2,  B256[o] * m2);
            acc[8 + o]  = fmaf(A256[o], s2h, B256[o] * m2h);
            acc[16 + o] = fmaf(A512[o], s1,  B512[o] * m1);
            acc[24 + o] = fmaf(A512[o], s1h, B512[o] * m1h);
        }

        // Butterfly transpose-reduce: after this, lane L holds z[L].
#pragma unroll
        for (int d = 16; d >= 1; d >>= 1) {
            bool up = (lane & d) != 0;
#pragma unroll
            for (int i = 0; i < d; i++) {
                float send = up ? acc[i] : acc[i + d];
                float other = __shfl_xor_sync(FULLMASK, send, d);
                acc[i] = (up ? acc[i + d] : acc[i]) + other;
            }
        }

        g_z[((size_t)r << 5) + lane] = acc[0];
    }
}

// ---------------------------------------------------------------------------
// Kernel 2a: H-axis Haar block moments. Warp per (img, 64-row block b).
// ---------------------------------------------------------------------------
__global__ void __launch_bounds__(256) k2a_colpass() {
    int tid = threadIdx.x, lane = tid & 31;
    int w = (blockIdx.x << 3) + (tid >> 5);  // 0..1023
    int img = w >> 4, b = w & 15;

    const float *zp = g_z + (((size_t)img << 10) + ((size_t)b << 6)) * 32 + lane;

    float s1 = 0, m1 = 0, s1h = 0, m1h = 0, s2 = 0, m2 = 0, s2h = 0, m2h = 0;
    float lop = 0.f;
#pragma unroll
    for (int k = 0; k < 32; k++) {
        float za = zp[(size_t)(k << 6)];
        float zb = zp[(size_t)(k << 6) + 32];
        float lo = za + zb, hi = za - zb;
        float fk = (float)k;
        s1 += lo;
        m1 = fmaf(fk, lo, m1);
        s1h += hi;
        m1h = fmaf(fk, hi, m1h);
        if (k & 1) {
            float lo2 = lop + lo, hi2 = lop - lo;
            float u2 = (float)(k >> 1);
            s2 += lo2;
            m2 = fmaf(u2, lo2, m2);
            s2h += hi2;
            m2h = fmaf(u2, hi2, m2h);
        } else {
            lop = lo;
        }
    }

    float *vp = g_V + (((size_t)(img * 16 + b)) << 8) + lane;
    vp[0] = s1;
    vp[32] = m1;
    vp[64] = s1h;
    vp[96] = m1h;
    vp[128] = s2;
    vp[160] = m2;
    vp[192] = s2h;
    vp[224] = m2h;
}

// ---------------------------------------------------------------------------
// Kernel 2b: per image: moments -> Y[32][32] -> feat(7 maps x 8x8) -> GEMM.
// ---------------------------------------------------------------------------
__global__ void __launch_bounds__(256)
    k2b_outpass(const float *__restrict__ Wg, const float *__restrict__ bias,
                float *__restrict__ out) {
    __shared__ float tA512[8 * 17], tB512[8 * 17], tA256[8 * 17], tB256[8 * 17];
    __shared__ float Vs[4096];     // [16 blocks][8 mt][32 cols]
    __shared__ float Ys[32 * 33];  // [row-group*8+o][col-group*8+oc], padded

    int tid = threadIdx.x;
    int img = blockIdx.x;
    fill_tables(tid, tA512, tB512, tA256, tB256);
    {
        const float4 *vg =
            reinterpret_cast<const float4 *>(g_V + ((size_t)img << 12));
        float4 *vs = reinterpret_cast<float4 *>(Vs);
#pragma unroll
        for (int i = 0; i < 4; i++) vs[tid + (i << 8)] = vg[tid + (i << 8)];
    }
    __syncthreads();

    // Stage 2: Y[ri][cb..cb+3]
    int ri = tid >> 3;
    int gr = ri >> 3, o = ri & 7;
    int cb = (tid & 7) << 2;
    const float *A = (gr < 2) ? tA256 : tA512;
    const float *B = (gr < 2) ? tB256 : tB512;
    int smt = ((gr < 2) ? 4 : 0) + ((gr & 1) << 1);
    float a0 = 0, a1 = 0, a2 = 0, a3 = 0;
#pragma unroll
    for (int t = 0; t < 16; t++) {
        float av = A[o * 17 + t], bv = B[o * 17 + t];
        const float *S = Vs + ((t << 3) + smt) * 32 + cb;
        const float *M = S + 32;
        a0 = fmaf(av, S[0], fmaf(bv, M[0], a0));
        a1 = fmaf(av, S[1], fmaf(bv, M[1], a1));
        a2 = fmaf(av, S[2], fmaf(bv, M[2], a2));
        a3 = fmaf(av, S[3], fmaf(bv, M[3], a3));
    }
    Ys[ri * 33 + cb + 0] = a0;
    Ys[ri * 33 + cb + 1] = a1;
    Ys[ri * 33 + cb + 2] = a2;
    Ys[ri * 33 + cb + 3] = a3;
    __syncthreads();

    // Stage 3: out[img][p][c], thread = channel c. Map (rowgroup,colgroup):
    // cA2(0,0) cH2(1,0) cV2(0,1) cD2(1,1) cH1(3,2) cV1(2,3) cD1(3,3)
    float w0 = Wg[tid], w1 = Wg[256 + tid], w2 = Wg[512 + tid],
          w3 = Wg[768 + tid], w4 = Wg[1024 + tid], w5 = Wg[1280 + tid],
          w6 = Wg[1536 + tid];
    float bb = bias[tid];
    float *op = out + ((size_t)img << 14) + tid;
#pragma unroll
    for (int p = 0; p < 64; p++) {
        int i = p >> 3, j = p & 7;
        float v = bb;
        v = fmaf(Ys[(0 + i) * 33 + (0 + j)], w0, v);
        v = fmaf(Ys[(8 + i) * 33 + (0 + j)], w1, v);
        v = fmaf(Ys[(0 + i) * 33 + (8 + j)], w2, v);
        v = fmaf(Ys[(8 + i) * 33 + (8 + j)], w3, v);
        v = fmaf(Ys[(24 + i) * 33 + (16 + j)], w4, v);
        v = fmaf(Ys[(16 + i) * 33 + (24 + j)], w5, v);
        v = fmaf(Ys[(24 + i) * 33 + (24 + j)], w6, v);
        op[(size_t)p << 8] = v;
    }
}

extern "C" void kernel_launch(void *const *d_in, const int *in_sizes, int n_in,
                              void *d_out, int out_size) {
    const float *x = (const float *)d_in[0];     // [64,1,1024,1024]
    const float *W = (const float *)d_in[1];     // [7,256]
    const float *bias = (const float *)d_in[2];  // [256]
    float *out = (float *)d_out;                 // [64,64,256]

    k1_rowpass<<<512, 128>>>(x);
    k2a_colpass<<<128, 256>>>();
    k2b_outpass<<<64, 256>>>(W, bias, out);
}

// round 3
// speedup vs baseline: 1.2924x; 1.2580x over previous
#include <cuda_runtime.h>

// ---------------------------------------------------------------------------
// WaveletEncoder: 2-level Haar wavedec2 -> bilinear(antialias) resize to 8x8
// -> stack 7 maps -> [B,64,7] @ W[7,256] + b.
//
// All-linear separable pipeline; W-axis and H-axis operators commute.
// Round-3 architecture:
//   k1 (column pass): per (img, 64-row block), accumulate the 8 H-axis
//       moment rows (level1 pair sum/ramp + level1 hi, level2 quad sum/ramp
//       + level2 hi) per column. Pure streaming, no cross-lane comms.
//       Writes M[64][16][8][1024] (32 MB).
//   k2 (row pass): W-axis Haar + triangle-resize on the 8192 M rows via
//       per-lane block moments + shfl butterfly. Writes V[8192][32].
//   k3 (=old k2b): per image, H-resize combine over the 16 blocks -> Y[32][32]
//       -> pick 7 maps' 8x8 feats -> fused GEMM with W[7,256] + bias.
// Haar 1/sqrt2 factors: W-axis folded in k2's coefficients, H-axis in k3's.
// ---------------------------------------------------------------------------

#define FULLMASK 0xffffffffu

__device__ float g_M[64u * 16u * 8u * 1024u];  // 32 MB H-moment rows
__device__ float g_V[64u * 16u * 8u * 32u];    // 1 MB  W-resized moments

// (a,b) such that w[o][block_start + u] = a + b*u within block t (size K/2).
static __device__ __forceinline__ void resize_ab(int o, int t, float K,
                                                 float invK, float fold,
                                                 float &a, float &b) {
    float tot = K * ((o == 0 || o == 7) ? 0.875f : 1.0f);
    float sf = (o + 0.5f) * K - 0.5f;
    float i0 = t * (K * 0.5f);
    float w0 = fmaxf(0.f, 1.f - fabsf(sf - i0) * invK);
    float w1 = fmaxf(0.f, 1.f - fabsf(sf - (i0 + 1.f)) * invK);
    float s = fold / tot;
    a = w0 * s;
    b = (w1 - w0) * s;
}

static __device__ __forceinline__ void fill_tables(int tid, float *tA512,
                                                   float *tB512, float *tA256,
                                                   float *tB256) {
    if (tid < 128) {
        int o = tid >> 4, t = tid & 15;
        float a, b;
        resize_ab(o, t, 64.f, 1.f / 64.f, 0.70710678118654752f, a, b);
        tA512[o * 17 + t] = a;
        tB512[o * 17 + t] = b;
    } else if (tid < 256) {
        int q = tid - 128;
        int o = q >> 4, t = q & 15;
        float a, b;
        resize_ab(o, t, 32.f, 1.f / 32.f, 0.5f, a, b);
        tA256[o * 17 + t] = a;
        tB256[o * 17 + t] = b;
    }
}

// ---------------------------------------------------------------------------
// Kernel 1: H-axis column pass. Block = (b, img), 256 threads x float4 = all
// 1024 columns. Streams 64 rows, accumulates 8 moment types per column.
// ---------------------------------------------------------------------------
__global__ void __launch_bounds__(256) k1_colpass(const float *__restrict__ x) {
    const int img = blockIdx.y, b = blockIdx.x;
    const int c4 = threadIdx.x;  // owns columns [4*c4, 4*c4+4)

    const float4 *xp = reinterpret_cast<const float4 *>(
                           x + (((size_t)img << 20) + ((size_t)b << 16))) +
                       c4;

    float4 s1 = {0, 0, 0, 0}, m1 = {0, 0, 0, 0};
    float4 s1h = {0, 0, 0, 0}, m1h = {0, 0, 0, 0};
    float4 s2 = {0, 0, 0, 0}, m2 = {0, 0, 0, 0};
    float4 s2h = {0, 0, 0, 0}, m2h = {0, 0, 0, 0};

#pragma unroll
    for (int pp = 0; pp < 16; pp++) {
        // rows 4pp .. 4pp+3 (row stride = 256 float4)
        float4 r0 = xp[(pp * 4 + 0) << 8];
        float4 r1 = xp[(pp * 4 + 1) << 8];
        float4 r2 = xp[(pp * 4 + 2) << 8];
        float4 r3 = xp[(pp * 4 + 3) << 8];
        const float p0 = (float)(2 * pp), p1 = (float)(2 * pp + 1);
        const float fpp = (float)pp;

#define COMP(f)                                                   \
    {                                                             \
        float lo0 = r0.f + r1.f, hi0 = r0.f - r1.f;               \
        float lo1 = r2.f + r3.f, hi1 = r2.f - r3.f;               \
        s1.f += lo0 + lo1;                                        \
        m1.f = fmaf(p0, lo0, m1.f);                               \
        m1.f = fmaf(p1, lo1, m1.f);                               \
        s1h.f += hi0 + hi1;                                       \
        m1h.f = fmaf(p0, hi0, m1h.f);                             \
        m1h.f = fmaf(p1, hi1, m1h.f);                             \
        float lo2 = lo0 + lo1, hi2 = lo0 - lo1;                   \
        s2.f += lo2;                                              \
        m2.f = fmaf(fpp, lo2, m2.f);                              \
        s2h.f += hi2;                                             \
        m2h.f = fmaf(fpp, hi2, m2h.f);                            \
    }
        COMP(x) COMP(y) COMP(z) COMP(w)
#undef COMP
    }

    float4 *mp = reinterpret_cast<float4 *>(
                     g_M + (((size_t)(img * 16 + b)) << 13)) +
                 c4;  // [mt][1024] rows, mt stride = 256 float4
    mp[0 << 8] = s1;
    mp[1 << 8] = m1;
    mp[2 << 8] = s1h;
    mp[3 << 8] = m1h;
    mp[4 << 8] = s2;
    mp[5 << 8] = m2;
    mp[6 << 8] = s2h;
    mp[7 << 8] = m2h;
}

// ---------------------------------------------------------------------------
// Kernel 2: W-axis row pass on the 8192 moment rows. Warp per row,
// per-lane analytic coefficients + shfl butterfly transpose-reduce.
// Output groups: g0=lo2res256, g1=hi2res256, g2=lo1res512, g3=hi1res512.
// ---------------------------------------------------------------------------
__global__ void __launch_bounds__(128) k2_rowpass() {
    const int lane = threadIdx.x & 31;
    const int gw = blockIdx.x * (blockDim.x >> 5) + (threadIdx.x >> 5);
    const int nwarps = gridDim.x * (blockDim.x >> 5);
    const int t = lane >> 1;

    float A512[8], B512[8], A256[8], B256[8];
#pragma unroll
    for (int o = 0; o < 8; o++) {
        resize_ab(o, t, 64.f, 1.f / 64.f, 0.70710678118654752f, A512[o], B512[o]);
        resize_ab(o, t, 32.f, 1.f / 32.f, 0.5f, A256[o], B256[o]);
    }

    const float off = (float)((lane & 1) << 4);
    const float off2 = (float)((lane & 1) << 3);

    for (int r = gw; r < 64 * 16 * 8; r += nwarps) {
        const float4 *xv =
            reinterpret_cast<const float4 *>(g_M + ((size_t)r << 10)) +
            (lane << 3);

        float4 v[8];
#pragma unroll
        for (int k = 0; k < 8; k++) v[k] = xv[k];

        float s1 = 0, m1 = 0, s1h = 0, m1h = 0, s2 = 0, m2 = 0, s2h = 0,
              m2h = 0;
#pragma unroll
        for (int k = 0; k < 8; k++) {
            float loa = v[k].x + v[k].y, lob = v[k].z + v[k].w;
            float hia = v[k].x - v[k].y, hib = v[k].z - v[k].w;
            float u = off + (float)(2 * k);
            s1 += loa + lob;
            m1 = fmaf(u, loa, m1);
            m1 = fmaf(u + 1.f, lob, m1);
            s1h += hia + hib;
            m1h = fmaf(u, hia, m1h);
            m1h = fmaf(u + 1.f, hib, m1h);
            float lo2 = loa + lob, hi2v = loa - lob;
            float u2 = off2 + (float)k;
            s2 += lo2;
            m2 = fmaf(u2, lo2, m2);
            s2h += hi2v;
            m2h = fmaf(u2, hi2v, m2h);
        }

        float acc[32];
#pragma unroll
        for (int o = 0; o < 8; o++) {
            acc[o] = fmaf(A256[o], s2, B256[o] * m2);
            acc[8 + o] = fmaf(A256[o], s2h, B256[o] * m2h);
            acc[16 + o] = fmaf(A512[o], s1, B512[o] * m1);
            acc[24 + o] = fmaf(A512[o], s1h, B512[o] * m1h);
        }

        // Butterfly transpose-reduce: lane L ends holding output z[L].
#pragma unroll
        for (int d = 16; d >= 1; d >>= 1) {
            bool up = (lane & d) != 0;
#pragma unroll
            for (int i = 0; i < d; i++) {
                float send = up ? acc[i] : acc[i + d];
                float other = __shfl_xor_sync(FULLMASK, send, d);
                acc[i] = (up ? acc[i + d] : acc[i]) + other;
            }
        }

        g_V[((size_t)r << 5) + lane] = acc[0];
    }
}

// ---------------------------------------------------------------------------
// Kernel 3: per image: V -> Y[32][32] -> feat(7 maps x 8x8) -> GEMM.
// ---------------------------------------------------------------------------
__global__ void __launch_bounds__(256)
    k3_outpass(const float *__restrict__ Wg, const float *__restrict__ bias,
               float *__restrict__ out) {
    __shared__ float tA512[8 * 17], tB512[8 * 17], tA256[8 * 17], tB256[8 * 17];
    __shared__ float Vs[4096];     // [16 blocks][8 mt][32 cols]
    __shared__ float Ys[32 * 33];  // [rowgroup*8+or][colgroup*8+oc]

    int tid = threadIdx.x;
    int img = blockIdx.x;
    fill_tables(tid, tA512, tB512, tA256, tB256);
    {
        const float4 *vg =
            reinterpret_cast<const float4 *>(g_V + ((size_t)img << 12));
        float4 *vs = reinterpret_cast<float4 *>(Vs);
#pragma unroll
        for (int i = 0; i < 4; i++) vs[tid + (i << 8)] = vg[tid + (i << 8)];
    }
    __syncthreads();

    // Stage 2: Y[ri][cb..cb+3]. Row groups use H moment types:
    // gr0 -> (s2,m2)@4, gr1 -> (s2h,m2h)@6, gr2 -> (s1,m1)@0, gr3 -> (s1h,m1h)@2
    int ri = tid >> 3;
    int gr = ri >> 3, o = ri & 7;
    int cb = (tid & 7) << 2;
    const float *A = (gr < 2) ? tA256 : tA512;
    const float *B = (gr < 2) ? tB256 : tB512;
    int smt = ((gr < 2) ? 4 : 0) + ((gr & 1) << 1);
    float a0 = 0, a1 = 0, a2 = 0, a3 = 0;
#pragma unroll
    for (int t = 0; t < 16; t++) {
        float av = A[o * 17 + t], bv = B[o * 17 + t];
        const float *S = Vs + ((t << 3) + smt) * 32 + cb;
        const float *M = S + 32;
        a0 = fmaf(av, S[0], fmaf(bv, M[0], a0));
        a1 = fmaf(av, S[1], fmaf(bv, M[1], a1));
        a2 = fmaf(av, S[2], fmaf(bv, M[2], a2));
        a3 = fmaf(av, S[3], fmaf(bv, M[3], a3));
    }
    Ys[ri * 33 + cb + 0] = a0;
    Ys[ri * 33 + cb + 1] = a1;
    Ys[ri * 33 + cb + 2] = a2;
    Ys[ri * 33 + cb + 3] = a3;
    __syncthreads();

    // Stage 3: map (rowgroup,colgroup):
    // cA2(0,0) cH2(1,0) cV2(0,1) cD2(1,1) cH1(3,2) cV1(2,3) cD1(3,3)
    float w0 = Wg[tid], w1 = Wg[256 + tid], w2 = Wg[512 + tid],
          w3 = Wg[768 + tid], w4 = Wg[1024 + tid], w5 = Wg[1280 + tid],
          w6 = Wg[1536 + tid];
    float bb = bias[tid];
    float *op = out + ((size_t)img << 14) + tid;
#pragma unroll
    for (int p = 0; p < 64; p++) {
        int i = p >> 3, j = p & 7;
        float v = bb;
        v = fmaf(Ys[(0 + i) * 33 + (0 + j)], w0, v);
        v = fmaf(Ys[(8 + i) * 33 + (0 + j)], w1, v);
        v = fmaf(Ys[(0 + i) * 33 + (8 + j)], w2, v);
        v = fmaf(Ys[(8 + i) * 33 + (8 + j)], w3, v);
        v = fmaf(Ys[(24 + i) * 33 + (16 + j)], w4, v);
        v = fmaf(Ys[(16 + i) * 33 + (24 + j)], w5, v);
        v = fmaf(Ys[(24 + i) * 33 + (24 + j)], w6, v);
        op[(size_t)p << 8] = v;
    }
}

extern "C" void kernel_launch(void *const *d_in, const int *in_sizes, int n_in,
                              void *d_out, int out_size) {
    const float *x = (const float *)d_in[0];     // [64,1,1024,1024]
    const float *W = (const float *)d_in[1];     // [7,256]
    const float *bias = (const float *)d_in[2];  // [256]
    float *out = (float *)d_out;                 // [64,64,256]

    dim3 g1(16, 64);
    k1_colpass<<<g1, 256>>>(x);
    k2_rowpass<<<512, 128>>>();
    k3_outpass<<<64, 256>>>(W, bias, out);
}

// round 4
// speedup vs baseline: 1.6600x; 1.2844x over previous
#include <cuda_runtime.h>

// ---------------------------------------------------------------------------
// WaveletEncoder: 2-level Haar wavedec2 -> bilinear(antialias) resize to 8x8
// -> stack 7 maps -> [B,64,7] @ W[7,256] + b.
//
// All-linear separable pipeline; W-axis and H-axis operators commute, and the
// triangle antialias resize weight is linear within blocks of K/2 samples, so
// each axis reduces to per-block (sum, ramp-moment) pairs.
//
// Round-4: single fused streaming kernel per (img, 64-row block):
//   - stream 64 rows, accumulate 8 H-axis moment types per column (registers)
//   - W-axis Haar (both levels intra-thread, 4 cols/thread) -> 8 W-partials
//     per H-moment type for W-block t = tid>>4
//   - 16-lane shfl butterfly per 16-value chunk reduces partials across each
//     half-warp (half-warp == W-block), 4KB smem staging
//   - final 256-thread combine with analytic resize coefficients -> V[imgb]
// k3: per image, V -> Y[32][32] -> 7 maps' 8x8 feats -> GEMM with W[7,256]+b.
// Haar 1/sqrt2 folds: W-axis in k1 coefficients, H-axis in k3 coefficients.
// ---------------------------------------------------------------------------

#define FULLMASK 0xffffffffu

__device__ float g_V[64u * 16u * 8u * 32u];  // 1 MB [imgb][8 mtH][32 z]

// (a,b) such that w[o][block_start + u] = a + b*u within block t (size K/2).
static __device__ __forceinline__ void resize_ab(int o, int t, float K,
                                                 float invK, float fold,
                                                 float &a, float &b) {
    float tot = K * ((o == 0 || o == 7) ? 0.875f : 1.0f);
    float sf = (o + 0.5f) * K - 0.5f;
    float i0 = t * (K * 0.5f);
    float w0 = fmaxf(0.f, 1.f - fabsf(sf - i0) * invK);
    float w1 = fmaxf(0.f, 1.f - fabsf(sf - (i0 + 1.f)) * invK);
    float s = fold / tot;
    a = w0 * s;
    b = (w1 - w0) * s;
}

static __device__ __forceinline__ void fill_tables(int tid, float *tA512,
                                                   float *tB512, float *tA256,
                                                   float *tB256) {
    if (tid < 128) {
        int o = tid >> 4, t = tid & 15;
        float a, b;
        resize_ab(o, t, 64.f, 1.f / 64.f, 0.70710678118654752f, a, b);
        tA512[o * 17 + t] = a;
        tB512[o * 17 + t] = b;
    } else if (tid < 256) {
        int q = tid - 128;
        int o = q >> 4, t = q & 15;
        float a, b;
        resize_ab(o, t, 32.f, 1.f / 32.f, 0.5f, a, b);
        tA256[o * 17 + t] = a;
        tB256[o * 17 + t] = b;
    }
}

// ---------------------------------------------------------------------------
// Fused kernel: H-moment streaming + in-block W-axis resize.
// ---------------------------------------------------------------------------
__global__ void __launch_bounds__(256) k1_fused(const float *__restrict__ x) {
    __shared__ float tA512[8 * 17], tB512[8 * 17], tA256[8 * 17], tB256[8 * 17];
    __shared__ float sm[16 * 64];  // [W-block t][mtH pair-chunk layout]

    const int tid = threadIdx.x;
    const int img = blockIdx.y, b = blockIdx.x;
    fill_tables(tid, tA512, tB512, tA256, tB256);

    const float4 *xp = reinterpret_cast<const float4 *>(
                           x + (((size_t)img << 20) + ((size_t)b << 16))) +
                       tid;

    float4 s1 = {0, 0, 0, 0}, m1 = {0, 0, 0, 0};
    float4 s1h = {0, 0, 0, 0}, m1h = {0, 0, 0, 0};
    float4 s2 = {0, 0, 0, 0}, m2 = {0, 0, 0, 0};
    float4 s2h = {0, 0, 0, 0}, m2h = {0, 0, 0, 0};

#pragma unroll
    for (int pp = 0; pp < 16; pp++) {
        float4 r0 = xp[(pp * 4 + 0) << 8];
        float4 r1 = xp[(pp * 4 + 1) << 8];
        float4 r2 = xp[(pp * 4 + 2) << 8];
        float4 r3 = xp[(pp * 4 + 3) << 8];
        const float p0 = (float)(2 * pp), p1 = (float)(2 * pp + 1);
        const float fpp = (float)pp;

#define COMP(f)                                       \
    {                                                 \
        float lo0 = r0.f + r1.f, hi0 = r0.f - r1.f;   \
        float lo1 = r2.f + r3.f, hi1 = r2.f - r3.f;   \
        s1.f += lo0 + lo1;                            \
        m1.f = fmaf(p0, lo0, m1.f);                   \
        m1.f = fmaf(p1, lo1, m1.f);                   \
        s1h.f += hi0 + hi1;                           \
        m1h.f = fmaf(p0, hi0, m1h.f);                 \
        m1h.f = fmaf(p1, hi1, m1h.f);                 \
        float lo2 = lo0 + lo1, hi2 = lo0 - lo1;       \
        s2.f += lo2;                                  \
        m2.f = fmaf(fpp, lo2, m2.f);                  \
        s2h.f += hi2;                                 \
        m2h.f = fmaf(fpp, hi2, m2h.f);                \
    }
        COMP(x) COMP(y) COMP(z) COMP(w)
#undef COMP
    }

    // ---- W-axis epilogue ----
    // Thread owns cols 4*tid..4*tid+3: W-level1 pairs j=2*tid, 2*tid+1;
    // W-level2 index i=tid. Block t = tid>>4 for both level sequences.
    const float u0 = (float)((2 * tid) & 31), u1 = u0 + 1.f;
    const float u2 = (float)(tid & 15);
    const int lane4 = tid & 15;
    float *smrow = sm + (tid >> 4) * 64;

    // Per chunk: two H-moment float4s -> 16 W-partials -> 16-lane butterfly
    // reduce over the half-warp -> lane l stores partial p=l.
#define CHUNK(c, A4, B4)                                                    \
    {                                                                       \
        float v[16];                                                        \
        {                                                                   \
            float l0 = A4.x + A4.y, h0 = A4.x - A4.y;                       \
            float l1 = A4.z + A4.w, h1 = A4.z - A4.w;                       \
            v[0] = l0 + l1;                                                 \
            v[1] = fmaf(u0, l0, u1 * l1);                                   \
            v[2] = h0 + h1;                                                 \
            v[3] = fmaf(u0, h0, u1 * h1);                                   \
            float lo2 = l0 + l1, hi2 = l0 - l1;                             \
            v[4] = lo2;                                                     \
            v[5] = u2 * lo2;                                                \
            v[6] = hi2;                                                     \
            v[7] = u2 * hi2;                                                \
        }                                                                   \
        {                                                                   \
            float l0 = B4.x + B4.y, h0 = B4.x - B4.y;                       \
            float l1 = B4.z + B4.w, h1 = B4.z - B4.w;                       \
            v[8] = l0 + l1;                                                 \
            v[9] = fmaf(u0, l0, u1 * l1);                                   \
            v[10] = h0 + h1;                                                \
            v[11] = fmaf(u0, h0, u1 * h1);                                  \
            float lo2 = l0 + l1, hi2 = l0 - l1;                             \
            v[12] = lo2;                                                    \
            v[13] = u2 * lo2;                                               \
            v[14] = hi2;                                                    \
            v[15] = u2 * hi2;                                               \
        }                                                                   \
        _Pragma("unroll") for (int d = 8; d >= 1; d >>= 1) {                \
            bool up = (tid & d) != 0;                                       \
            _Pragma("unroll") for (int i = 0; i < d; i++) {                 \
                float send = up ? v[i] : v[i + d];                          \
                float other = __shfl_xor_sync(FULLMASK, send, d);           \
                v[i] = (up ? v[i + d] : v[i]) + other;                      \
            }                                                               \
        }                                                                   \
        smrow[(c) * 16 + lane4] = v[0];                                     \
    }

    CHUNK(0, s1, m1)
    CHUNK(1, s1h, m1h)
    CHUNK(2, s2, m2)
    CHUNK(3, s2h, m2h)
#undef CHUNK

    __syncthreads();

    // Final combine: thread = (mtH = tid>>5, z = tid&31), z = g*8+o.
    // sm layout: [t][ (mtH>>1)*16 + (mtH&1)*8 + w ], w-pairs per group:
    // g0(lo2res,256)->w4,5  g1(hi2res,256)->w6,7
    // g2(lo1res,512)->w0,1  g3(hi1res,512)->w2,3
    {
        int mtH = tid >> 5, z = tid & 31, g = z >> 3, o = z & 7;
        const float *A = (g < 2) ? tA256 : tA512;
        const float *B = (g < 2) ? tB256 : tB512;
        int wb = (g & 2) ? ((g & 1) ? 2 : 0) : ((g & 1) ? 6 : 4);
        const float *base = sm + (mtH >> 1) * 16 + (mtH & 1) * 8 + wb;
        float acc = 0.f;
#pragma unroll
        for (int t = 0; t < 16; t++)
            acc = fmaf(A[o * 17 + t], base[t * 64],
                       fmaf(B[o * 17 + t], base[t * 64 + 1], acc));
        g_V[(((size_t)(img * 16 + b)) << 8) + tid] = acc;
    }
}

// ---------------------------------------------------------------------------
// Kernel 3: per image: V -> Y[32][32] -> feat(7 maps x 8x8) -> GEMM.
// ---------------------------------------------------------------------------
__global__ void __launch_bounds__(256)
    k3_outpass(const float *__restrict__ Wg, const float *__restrict__ bias,
               float *__restrict__ out) {
    __shared__ float tA512[8 * 17], tB512[8 * 17], tA256[8 * 17], tB256[8 * 17];
    __shared__ float Vs[4096];     // [16 blocks][8 mt][32 z]
    __shared__ float Ys[32 * 33];  // [rowgroup*8+or][colgroup*8+oc]

    int tid = threadIdx.x;
    int img = blockIdx.x;
    fill_tables(tid, tA512, tB512, tA256, tB256);
    {
        const float4 *vg =
            reinterpret_cast<const float4 *>(g_V + ((size_t)img << 12));
        float4 *vs = reinterpret_cast<float4 *>(Vs);
#pragma unroll
        for (int i = 0; i < 4; i++) vs[tid + (i << 8)] = vg[tid + (i << 8)];
    }
    __syncthreads();

    // Stage 2: Y[ri][cb..cb+3]. Row groups use H moment types:
    // gr0->(s2,m2)@4 gr1->(s2h,m2h)@6 gr2->(s1,m1)@0 gr3->(s1h,m1h)@2
    int ri = tid >> 3;
    int gr = ri >> 3, o = ri & 7;
    int cb = (tid & 7) << 2;
    const float *A = (gr < 2) ? tA256 : tA512;
    const float *B = (gr < 2) ? tB256 : tB512;
    int smt = ((gr < 2) ? 4 : 0) + ((gr & 1) << 1);
    float a0 = 0, a1 = 0, a2 = 0, a3 = 0;
#pragma unroll
    for (int t = 0; t < 16; t++) {
        float av = A[o * 17 + t], bv = B[o * 17 + t];
        const float *S = Vs + ((t << 3) + smt) * 32 + cb;
        const float *M = S + 32;
        a0 = fmaf(av, S[0], fmaf(bv, M[0], a0));
        a1 = fmaf(av, S[1], fmaf(bv, M[1], a1));
        a2 = fmaf(av, S[2], fmaf(bv, M[2], a2));
        a3 = fmaf(av, S[3], fmaf(bv, M[3], a3));
    }
    Ys[ri * 33 + cb + 0] = a0;
    Ys[ri * 33 + cb + 1] = a1;
    Ys[ri * 33 + cb + 2] = a2;
    Ys[ri * 33 + cb + 3] = a3;
    __syncthreads();

    // Stage 3: map (rowgroup,colgroup):
    // cA2(0,0) cH2(1,0) cV2(0,1) cD2(1,1) cH1(3,2) cV1(2,3) cD1(3,3)
    float w0 = Wg[tid], w1 = Wg[256 + tid], w2 = Wg[512 + tid],
          w3 = Wg[768 + tid], w4 = Wg[1024 + tid], w5 = Wg[1280 + tid],
          w6 = Wg[1536 + tid];
    float bb = bias[tid];
    float *op = out + ((size_t)img << 14) + tid;
#pragma unroll
    for (int p = 0; p < 64; p++) {
        int i = p >> 3, j = p & 7;
        float v = bb;
        v = fmaf(Ys[(0 + i) * 33 + (0 + j)], w0, v);
        v = fmaf(Ys[(8 + i) * 33 + (0 + j)], w1, v);
        v = fmaf(Ys[(0 + i) * 33 + (8 + j)], w2, v);
        v = fmaf(Ys[(8 + i) * 33 + (8 + j)], w3, v);
        v = fmaf(Ys[(24 + i) * 33 + (16 + j)], w4, v);
        v = fmaf(Ys[(16 + i) * 33 + (24 + j)], w5, v);
        v = fmaf(Ys[(24 + i) * 33 + (24 + j)], w6, v);
        op[(size_t)p << 8] = v;
    }
}

extern "C" void kernel_launch(void *const *d_in, const int *in_sizes, int n_in,
                              void *d_out, int out_size) {
    const float *x = (const float *)d_in[0];     // [64,1,1024,1024]
    const float *W = (const float *)d_in[1];     // [7,256]
    const float *bias = (const float *)d_in[2];  // [256]
    float *out = (float *)d_out;                 // [64,64,256]

    dim3 g1(16, 64);
    k1_fused<<<g1, 256>>>(x);
    k3_outpass<<<64, 256>>>(W, bias, out);
}